// round 13
// baseline (speedup 1.0000x reference)
#include <cuda_runtime.h>
#include <cstdint>
#include <math.h>

#define HID 1024
#define EMB 1024
#define MAXLEN 4096
#define VOCAB 50257
#define NBLK 148
#define NTHR 1024
#define NPART 8
#define NWARPS (NBLK * 32)    // 4736 warps
#define ROWS_PB 340           // fc2 rows per block (148*340 = 50320 >= 50257)
#define DYN_SMEM (2 * 16 * 1024 * 4)   // 2 stages x 16 rows x 4KB = 131072 B

// ---------------- device scratch ----------------
__device__ float g_gates[4 * HID];
__device__ float g_scores[MAXLEN];
__device__ float g_ctx_part[NPART * HID];
__device__ float g_hid[HID];
__device__ float g_lse_m[NBLK];
__device__ float g_lse_l[NBLK];
__device__ unsigned long long g_bar = 0ULL;   // monotonic ticket counter (never reset)

__device__ __forceinline__ float warp_sum(float v) {
#pragma unroll
    for (int o = 16; o; o >>= 1) v += __shfl_down_sync(0xffffffffu, v, o);
    return v;
}
__device__ __forceinline__ float warp_max(float v) {
#pragma unroll
    for (int o = 16; o; o >>= 1) v = fmaxf(v, __shfl_down_sync(0xffffffffu, v, o));
    return v;
}

// deterministic, reset-free grid barrier (148 blocks, 1/SM, co-resident)
__device__ __forceinline__ void grid_barrier() {
    __syncthreads();
    if (threadIdx.x == 0) {
        __threadfence();
        unsigned long long ticket = atomicAdd(&g_bar, 1ULL);
        unsigned long long target = (ticket / NBLK + 1ULL) * (unsigned long long)NBLK;
        while (*(volatile unsigned long long*)&g_bar < target) { }
    }
    __syncthreads();
}

__device__ __forceinline__ void cp_async16(unsigned int dst, const void* src) {
    asm volatile("cp.async.cg.shared.global [%0], [%1], 16;\n" :: "r"(dst), "l"(src));
}

// issue one 16-row stage of fc2_w into dyn smem buffer (all threads participate)
__device__ __forceinline__ void issue_stage(const float* __restrict__ fc2_w,
                                            float4* dyn4, int s, int start, int end, int tid) {
    int r0 = start + (s << 4);
    float4* buf = dyn4 + ((s & 1) << 12);          // 4096 float4 per stage
    unsigned int sbase = (unsigned int)__cvta_generic_to_shared(buf);
#pragma unroll
    for (int i = 0; i < 4; i++) {
        int idx = tid + (i << 10);                 // 0..4095 float4 slots
        int row = idx >> 8;                        // 0..15
        if (r0 + row < end)
            cp_async16(sbase + idx * 16,
                       fc2_w + (size_t)(r0 + row) * HID + ((idx & 255) << 2));
    }
    asm volatile("cp.async.commit_group;\n" ::: "memory");
}

__global__ __launch_bounds__(NTHR, 1)
void fused_all(const float* __restrict__ A, const float* __restrict__ x,
               const float* __restrict__ h, const float* __restrict__ c,
               const float* __restrict__ W_ih, const float* __restrict__ W_hh,
               const float* __restrict__ b_ih, const float* __restrict__ b_hh,
               const float* __restrict__ fc1_w, const float* __restrict__ fc1_b,
               const float* __restrict__ fc2_w, const float* __restrict__ fc2_b,
               float* __restrict__ out)
{
    extern __shared__ __align__(16) float4 dyn4[];  // 128 KB stage buffers

    __shared__ __align__(16) float svec[2 * HID];   // 8 KB staging
    __shared__ __align__(16) float shnew[HID];      // block-local h_new
    __shared__ __align__(16) float sws[512];        // softmax weights
    __shared__ float sred[16][64];                  // ctx / fc1 / fc2 partial reduce
    __shared__ float sredw[32];
    __shared__ float sredw2[32];

    const int tid = threadIdx.x;
    const int b = blockIdx.x;
    const int w = tid >> 5, lane = tid & 31;

    // ================= Phase 1: gate-row GEMV across ALL 148 blocks =================
    {
        svec[tid] = x[tid];
        svec[HID + tid] = h[tid];
        __syncthreads();
        int r = w * NBLK + b;                    // 0..4735, gate-row
        if (r < 4 * HID) {
            const float4* rW = (const float4*)(W_ih + (size_t)r * EMB);
            const float4* rU = (const float4*)(W_hh + (size_t)r * HID);
            const float4* x4 = (const float4*)svec;
            const float4* h4 = (const float4*)(svec + HID);
            float a = 0.f;
#pragma unroll
            for (int k = lane; k < 256; k += 32) {
                float4 wv = __ldcs(rW + k), xv = x4[k];
                a += wv.x * xv.x + wv.y * xv.y + wv.z * xv.z + wv.w * xv.w;
                float4 uv = __ldcs(rU + k), hv = h4[k];
                a += uv.x * hv.x + uv.y * hv.y + uv.z * hv.z + uv.w * hv.w;
            }
            a = warp_sum(a);
            if (lane == 0) g_gates[r] = a;
        }
    }
    grid_barrier();

    // ================= Phase 2a: LSTM pointwise, redundant per block -> shnew =================
    {
        int j = tid;
        float gi = g_gates[j]           + b_ih[j]           + b_hh[j];
        float gf = g_gates[HID + j]     + b_ih[HID + j]     + b_hh[HID + j];
        float gg = g_gates[2 * HID + j] + b_ih[2 * HID + j] + b_hh[2 * HID + j];
        float go = g_gates[3 * HID + j] + b_ih[3 * HID + j] + b_hh[3 * HID + j];
        float ig = 1.f / (1.f + expf(-gi));
        float fg = 1.f / (1.f + expf(-gf));
        float gt = tanhf(gg);
        float og = 1.f / (1.f + expf(-go));
        float cn = fg * c[j] + ig * gt;
        float hn = og * tanhf(cn);
        shnew[j] = hn;
        if (b == 0) {
            out[VOCAB + j] = hn;          // h_new
            out[VOCAB + HID + j] = cn;    // c_new
        }
        __syncthreads();
    }

    // ================= Phase 2b: scores[t] = A[t,:] . h_new (all 148 blocks) =================
    {
        int t = w * NBLK + b;                    // 0..4735
        if (t < MAXLEN) {
            const float4* r = (const float4*)(A + (size_t)t * HID);
            const float4* h4 = (const float4*)shnew;
            float a = 0.f;
#pragma unroll
            for (int k = lane; k < 256; k += 32) {
                float4 v = r[k], hv = h4[k];
                a += v.x * hv.x + v.y * hv.y + v.z * hv.z + v.w * hv.w;
            }
            a = warp_sum(a);
            if (lane == 0) g_scores[t] = a;
        }
    }
    grid_barrier();

    // ================= Phase 3: softmax stats (redundant per block) + ctx partials (blocks 0..127) =================
    if (b < 128) {
        float m, inv_l;
        {
            float mm = -INFINITY;
#pragma unroll
            for (int i = 0; i < 4; i++) mm = fmaxf(mm, g_scores[tid + i * 1024]);
            mm = warp_max(mm);
            if (lane == 0) sredw[w] = mm;
            __syncthreads();
            if (w == 0) {
                float v = sredw[lane];
                v = warp_max(v);
                if (lane == 0) sredw[0] = v;
            }
            __syncthreads();
            m = sredw[0];
            __syncthreads();

            float l = 0.f;
#pragma unroll
            for (int i = 0; i < 4; i++) l += expf(g_scores[tid + i * 1024] - m);
            l = warp_sum(l);
            if (lane == 0) sredw2[w] = l;
            __syncthreads();
            if (w == 0) {
                float v = sredw2[lane];
                v = warp_sum(v);
                if (lane == 0) sredw2[0] = 1.f / v;
            }
            __syncthreads();
            inv_l = sredw2[0];
        }
        {
            int bt = b >> 4;                         // t-chunk 0..7 (512 t each)
            int bd = b & 15;                         // d-chunk 0..15 (64 d each)
            int t0 = bt * 512;
            if (tid < 512) sws[tid] = expf(g_scores[t0 + tid] - m) * inv_l;
            __syncthreads();

            int tsub = tid >> 6;                     // 0..15, 32 t each
            int dl = tid & 63;
            int d = bd * 64 + dl;
            float acc = 0.f;
            int tb = tsub * 32;
#pragma unroll 4
            for (int t = 0; t < 32; t++)
                acc += A[(size_t)(t0 + tb + t) * HID + d] * sws[tb + t];
            sred[tsub][dl] = acc;
            __syncthreads();
            if (tid < 64) {
                float v = 0.f;
#pragma unroll
                for (int k2 = 0; k2 < 16; k2++) v += sred[k2][tid];
                g_ctx_part[bt * HID + bd * 64 + tid] = v;
            }
        }
    }
    grid_barrier();

    // ================= Phase 4: fc1 (fused ctx reduce; blocks 0..127, 8 rows each) =================
    if (b < 128) {
        float4* sc4 = (float4*)svec;
        if (tid < 256) {
            const float4* part4 = (const float4*)g_ctx_part;
            float4 a = part4[tid];
#pragma unroll
            for (int s = 1; s < NPART; s++) {
                float4 p = part4[s * 256 + tid];
                a.x += p.x; a.y += p.y; a.z += p.z; a.w += p.w;
            }
            sc4[tid] = a;
        } else if (tid < 512) {
            sc4[tid] = ((const float4*)shnew)[tid - 256];
        }
        __syncthreads();

        int jl = w >> 2;                         // row within block 0..7
        int q = w & 3;                           // quarter of K
        int j = b * 8 + jl;
        const float4* r = (const float4*)(fc1_w + (size_t)j * 2 * HID);
        float a = 0.f;
#pragma unroll
        for (int k = q * 128 + lane; k < (q + 1) * 128; k += 32) {
            float4 v = __ldcs(r + k), cv = sc4[k];
            a += v.x * cv.x + v.y * cv.y + v.z * cv.z + v.w * cv.w;
        }
        a = warp_sum(a);
        if (lane == 0) sred[0][w] = a;
        __syncthreads();
        if (tid < 8) {
            float v = sred[0][tid * 4] + sred[0][tid * 4 + 1] +
                      sred[0][tid * 4 + 2] + sred[0][tid * 4 + 3];
            g_hid[b * 8 + tid] = v + fc1_b[b * 8 + tid];
        }
    }
    grid_barrier();

    // ================= Phase 5: fc2 via cp.async staged pipeline + per-block LSE =================
    {
        svec[tid] = g_hid[tid];
        __syncthreads();
        const float4* h4 = (const float4*)svec;

        const int start = b * ROWS_PB;
        const int end = (start + ROWS_PB < VOCAB) ? start + ROWS_PB : VOCAB;
        const int nrows = end - start;
        const int ns = (nrows + 15) >> 4;        // 16-row stages

        float lm = -INFINITY, ll = 0.f;          // warp-0 lanes 0..15 track per-slot LSE

        if (ns > 0) issue_stage(fc2_w, dyn4, 0, start, end, tid);
        for (int s = 0; s < ns; s++) {
            if (s + 1 < ns) {
                issue_stage(fc2_w, dyn4, s + 1, start, end, tid);
                asm volatile("cp.async.wait_group 1;\n" ::: "memory");
            } else {
                asm volatile("cp.async.wait_group 0;\n" ::: "memory");
            }
            __syncthreads();

            const float4* buf = dyn4 + ((s & 1) << 12);
            int r0 = start + (s << 4);
            int rl = w >> 1, half = w & 1;       // 2 warps per row
            float a = 0.f;
            if (r0 + rl < end) {
                const float4* rowp = buf + (rl << 8);
#pragma unroll
                for (int i = 0; i < 4; i++) {
                    int k = (half << 7) + lane + (i << 5);
                    float4 v = rowp[k], hv = h4[k];
                    a += v.x * hv.x + v.y * hv.y + v.z * hv.z + v.w * hv.w;
                }
            }
            a = warp_sum(a);
            if (lane == 0) sred[rl][half] = a;
            __syncthreads();

            if (w == 0 && lane < 16) {
                int r = r0 + lane;
                if (r < end) {
                    float logit = sred[lane][0] + sred[lane][1] + fc2_b[r];
                    out[r] = logit;
                    float mm = fmaxf(lm, logit);
                    ll = ll * expf(lm - mm) + expf(logit - mm);
                    lm = mm;
                }
            }
            __syncthreads();                     // buffer (s&1) free for stage s+2
        }

        if (w == 0) {
#pragma unroll
            for (int o = 16; o; o >>= 1) {
                float m2 = __shfl_down_sync(0xffffffffu, lm, o);
                float l2 = __shfl_down_sync(0xffffffffu, ll, o);
                float M = fmaxf(lm, m2);
                ll = ll * expf(lm - M) + l2 * expf(m2 - M);
                lm = M;
            }
            if (lane == 0) { g_lse_m[b] = lm; g_lse_l[b] = ll; }
        }
    }
    grid_barrier();

    // ================= Phase 6: LSE combine (redundant per block) + float4 subtract =================
    {
        if (w == 0) {
            float mm = -INFINITY, lll = 0.f;
            for (int i = lane; i < NBLK; i += 32) {
                float m2 = g_lse_m[i], l2 = g_lse_l[i];
                float M = fmaxf(mm, m2);
                lll = lll * expf(mm - M) + l2 * expf(m2 - M);
                mm = M;
            }
#pragma unroll
            for (int o = 16; o; o >>= 1) {
                float m2 = __shfl_down_sync(0xffffffffu, mm, o);
                float l2 = __shfl_down_sync(0xffffffffu, lll, o);
                float M = fmaxf(mm, m2);
                lll = lll * expf(mm - M) + l2 * expf(m2 - M);
                mm = M;
            }
            if (lane == 0) sredw[0] = mm + logf(lll);
        }
        __syncthreads();
        float lse = sredw[0];
        const int N4 = VOCAB / 4;                // 12564
        int i4 = b * NTHR + tid;
        float4* o4 = (float4*)out;
        if (i4 < N4) {
            float4 v = o4[i4];
            v.x -= lse; v.y -= lse; v.z -= lse; v.w -= lse;
            o4[i4] = v;
        } else if (i4 == N4) {
            out[VOCAB - 1] -= lse;               // tail element
        }
    }
}

// ---------------- launch ----------------
extern "C" void kernel_launch(void* const* d_in, const int* in_sizes, int n_in,
                              void* d_out, int out_size) {
    const float* attn  = (const float*)d_in[0];
    const float* x     = (const float*)d_in[1];
    const float* h     = (const float*)d_in[2];
    const float* c     = (const float*)d_in[3];
    const float* W_ih  = (const float*)d_in[4];
    const float* W_hh  = (const float*)d_in[5];
    const float* b_ih  = (const float*)d_in[6];
    const float* b_hh  = (const float*)d_in[7];
    const float* fc1_w = (const float*)d_in[8];
    const float* fc1_b = (const float*)d_in[9];
    const float* fc2_w = (const float*)d_in[10];
    const float* fc2_b = (const float*)d_in[11];
    float* out = (float*)d_out;

    cudaFuncSetAttribute(fused_all, cudaFuncAttributeMaxDynamicSharedMemorySize, DYN_SMEM);
    fused_all<<<NBLK, NTHR, DYN_SMEM>>>(attn, x, h, c, W_ih, W_hh, b_ih, b_hh,
                                        fc1_w, fc1_b, fc2_w, fc2_b, out);
}

// round 14
// speedup vs baseline: 1.1308x; 1.1308x over previous
#include <cuda_runtime.h>
#include <cstdint>
#include <math.h>

#define HID 1024
#define EMB 1024
#define MAXLEN 4096
#define VOCAB 50257
#define NBLK 148
#define NTHR 512
#define NPART 8
#define WTOT (NBLK * 16)      // 2368 warps total

// ---------------- device scratch ----------------
__device__ float g_gates[4 * HID];
__device__ float g_scores[MAXLEN];
__device__ float g_ctx_part[NPART * HID];
__device__ float g_hid[HID];
__device__ float g_lse_m[NBLK];
__device__ float g_lse_l[NBLK];
__device__ unsigned long long g_bar = 0ULL;   // monotonic ticket counter (never reset)

__device__ __forceinline__ float warp_sum(float v) {
#pragma unroll
    for (int o = 16; o; o >>= 1) v += __shfl_down_sync(0xffffffffu, v, o);
    return v;
}
__device__ __forceinline__ float warp_max(float v) {
#pragma unroll
    for (int o = 16; o; o >>= 1) v = fmaxf(v, __shfl_down_sync(0xffffffffu, v, o));
    return v;
}

// deterministic, reset-free grid barrier (148 blocks, 1/SM, co-resident)
__device__ __forceinline__ void grid_barrier() {
    __syncthreads();
    if (threadIdx.x == 0) {
        __threadfence();
        unsigned long long ticket = atomicAdd(&g_bar, 1ULL);
        unsigned long long target = (ticket / NBLK + 1ULL) * (unsigned long long)NBLK;
        while (*(volatile unsigned long long*)&g_bar < target) { }
    }
    __syncthreads();
}

__global__ __launch_bounds__(NTHR, 1)
void fused_all(const float* __restrict__ A, const float* __restrict__ x,
               const float* __restrict__ h, const float* __restrict__ c,
               const float* __restrict__ W_ih, const float* __restrict__ W_hh,
               const float* __restrict__ b_ih, const float* __restrict__ b_hh,
               const float* __restrict__ fc1_w, const float* __restrict__ fc1_b,
               const float* __restrict__ fc2_w, const float* __restrict__ fc2_b,
               float* __restrict__ out)
{
    __shared__ __align__(16) float svec[2 * HID];   // 8 KB staging
    __shared__ __align__(16) float shnew[HID];      // block-local h_new
    __shared__ __align__(16) float sws[512];        // softmax weights
    __shared__ float sred[8][64];                   // ctx partial reduce
    __shared__ float sredw[32];
    __shared__ float sredw2[32];

    const int tid = threadIdx.x;
    const int b = blockIdx.x;
    const int w = tid >> 5, lane = tid & 31;        // 16 warps

    // ================= Phase 1: gate-row GEMV, 2 rows/warp interleaved =================
    {
        svec[tid] = x[tid];
        svec[tid + 512] = x[tid + 512];
        svec[HID + tid] = h[tid];
        svec[HID + tid + 512] = h[tid + 512];
        __syncthreads();
        const float4* x4 = (const float4*)svec;
        const float4* h4 = (const float4*)(svec + HID);

        int r0 = w * NBLK + b;                   // 0..2367
        int r1 = r0 + WTOT;                      // 2368..4735 (may be >= 4096)
        bool has1 = (r1 < 4 * HID);
        const float4* rW0 = (const float4*)(W_ih + (size_t)r0 * EMB);
        const float4* rU0 = (const float4*)(W_hh + (size_t)r0 * HID);
        const float4* rW1 = (const float4*)(W_ih + (size_t)(has1 ? r1 : r0) * EMB);
        const float4* rU1 = (const float4*)(W_hh + (size_t)(has1 ? r1 : r0) * HID);
        float a0 = 0.f, a1 = 0.f;
#pragma unroll
        for (int i = 0; i < 8; i++) {
            int k = lane + (i << 5);
            float4 xv = x4[k], hv = h4[k];
            float4 w0 = __ldcs(rW0 + k), u0 = __ldcs(rU0 + k);
            float4 w1 = __ldcs(rW1 + k), u1 = __ldcs(rU1 + k);
            a0 += w0.x * xv.x + w0.y * xv.y + w0.z * xv.z + w0.w * xv.w
                + u0.x * hv.x + u0.y * hv.y + u0.z * hv.z + u0.w * hv.w;
            a1 += w1.x * xv.x + w1.y * xv.y + w1.z * xv.z + w1.w * xv.w
                + u1.x * hv.x + u1.y * hv.y + u1.z * hv.z + u1.w * hv.w;
        }
        a0 = warp_sum(a0);
        a1 = warp_sum(a1);
        if (lane == 0) {
            g_gates[r0] = a0;
            if (has1) g_gates[r1] = a1;
        }
    }
    grid_barrier();

    // ================= Phase 2a: LSTM pointwise, redundant per block -> shnew =================
    {
#pragma unroll
        for (int jj = 0; jj < 2; jj++) {
            int j = tid + jj * 512;
            float gi = g_gates[j]           + b_ih[j]           + b_hh[j];
            float gf = g_gates[HID + j]     + b_ih[HID + j]     + b_hh[HID + j];
            float gg = g_gates[2 * HID + j] + b_ih[2 * HID + j] + b_hh[2 * HID + j];
            float go = g_gates[3 * HID + j] + b_ih[3 * HID + j] + b_hh[3 * HID + j];
            float ig = 1.f / (1.f + expf(-gi));
            float fg = 1.f / (1.f + expf(-gf));
            float gt = tanhf(gg);
            float og = 1.f / (1.f + expf(-go));
            float cn = fg * c[j] + ig * gt;
            float hn = og * tanhf(cn);
            shnew[j] = hn;
            if (b == 0) {
                out[VOCAB + j] = hn;          // h_new
                out[VOCAB + HID + j] = cn;    // c_new
            }
        }
        __syncthreads();
    }

    // ================= Phase 2b: scores, 2 rows/warp, register-resident h_new =================
    {
        const float4* s4 = (const float4*)shnew;
        float4 hreg[8];
#pragma unroll
        for (int i = 0; i < 8; i++) hreg[i] = s4[lane + (i << 5)];

        int t0 = w * NBLK + b;                   // 0..2367
        int t1 = t0 + WTOT;
        bool has1 = (t1 < MAXLEN);
        const float4* p0 = (const float4*)(A + (size_t)t0 * HID);
        const float4* p1 = (const float4*)(A + (size_t)(has1 ? t1 : t0) * HID);
        float a0 = 0.f, a1 = 0.f;
#pragma unroll
        for (int i = 0; i < 8; i++) {
            int k = lane + (i << 5);
            float4 v0 = p0[k], v1 = p1[k];
            a0 += v0.x * hreg[i].x + v0.y * hreg[i].y + v0.z * hreg[i].z + v0.w * hreg[i].w;
            a1 += v1.x * hreg[i].x + v1.y * hreg[i].y + v1.z * hreg[i].z + v1.w * hreg[i].w;
        }
        a0 = warp_sum(a0);
        a1 = warp_sum(a1);
        if (lane == 0) {
            g_scores[t0] = a0;
            if (has1) g_scores[t1] = a1;
        }
    }
    grid_barrier();

    // ================= Phase 3: softmax stats (redundant per block) + ctx partials (blocks 0..127) =================
    if (b < 128) {
        float m, inv_l;
        {
            float mm = -INFINITY;
#pragma unroll
            for (int i = 0; i < 8; i++) mm = fmaxf(mm, g_scores[tid + i * 512]);
            mm = warp_max(mm);
            if (lane == 0) sredw[w] = mm;
            __syncthreads();
            if (w == 0) {
                float v = (lane < 16) ? sredw[lane] : -INFINITY;
                v = warp_max(v);
                if (lane == 0) sredw[0] = v;
            }
            __syncthreads();
            m = sredw[0];
            __syncthreads();

            float l = 0.f;
#pragma unroll
            for (int i = 0; i < 8; i++) l += expf(g_scores[tid + i * 512] - m);
            l = warp_sum(l);
            if (lane == 0) sredw2[w] = l;
            __syncthreads();
            if (w == 0) {
                float v = (lane < 16) ? sredw2[lane] : 0.f;
                v = warp_sum(v);
                if (lane == 0) sredw2[0] = 1.f / v;
            }
            __syncthreads();
            inv_l = sredw2[0];
        }
        {
            int bt = b >> 4;                         // t-chunk 0..7 (512 t each)
            int bd = b & 15;                         // d-chunk 0..15 (64 d each)
            int t0 = bt * 512;
            sws[tid] = expf(g_scores[t0 + tid] - m) * inv_l;
            __syncthreads();

            int tsub = tid >> 6;                     // 0..7, 64 t each
            int dl = tid & 63;
            int d = bd * 64 + dl;
            float acc = 0.f;
            int tb = tsub * 64;
#pragma unroll 4
            for (int t = 0; t < 64; t++)
                acc += A[(size_t)(t0 + tb + t) * HID + d] * sws[tb + t];
            sred[tsub][dl] = acc;
            __syncthreads();
            if (tid < 64) {
                float v = 0.f;
#pragma unroll
                for (int k2 = 0; k2 < 8; k2++) v += sred[k2][tid];
                g_ctx_part[bt * HID + bd * 64 + tid] = v;
            }
        }
    }
    grid_barrier();

    // ================= Phase 4: fc1 (fused ctx reduce; blocks 0..127, 8 rows, 2 warps/row) =================
    if (b < 128) {
        float4* sc4 = (float4*)svec;
        if (tid < 256) {
            const float4* part4 = (const float4*)g_ctx_part;
            float4 a = part4[tid];
#pragma unroll
            for (int s = 1; s < NPART; s++) {
                float4 p = part4[s * 256 + tid];
                a.x += p.x; a.y += p.y; a.z += p.z; a.w += p.w;
            }
            sc4[tid] = a;
        } else {
            sc4[tid] = ((const float4*)shnew)[tid - 256];
        }
        __syncthreads();

        int jl = w >> 1;                         // row within block 0..7
        int half = w & 1;                        // half of K
        int j = b * 8 + jl;
        const float4* r = (const float4*)(fc1_w + (size_t)j * 2 * HID);
        float a = 0.f;
#pragma unroll
        for (int i = 0; i < 8; i++) {
            int k = half * 256 + lane + (i << 5);
            float4 v = __ldcs(r + k), cv = sc4[k];
            a += v.x * cv.x + v.y * cv.y + v.z * cv.z + v.w * cv.w;
        }
        a = warp_sum(a);
        if (lane == 0) sredw[w] = a;
        __syncthreads();
        if (tid < 8) {
            g_hid[b * 8 + tid] = sredw[tid * 2] + sredw[tid * 2 + 1] + fc1_b[b * 8 + tid];
        }
    }
    grid_barrier();

    // ================= Phase 5: fc2, 4 rows/warp interleaved, register-resident hid =================
    {
        svec[tid] = g_hid[tid];
        svec[tid + 512] = g_hid[tid + 512];
        __syncthreads();
        const float4* s4 = (const float4*)svec;
        float4 hreg[8];
#pragma unroll
        for (int i = 0; i < 8; i++) hreg[i] = s4[lane + (i << 5)];

        int gw = b * 16 + w;                     // global warp 0..2367
        float lm = -INFINITY, ll = 0.f;
        for (int r0 = gw; r0 < VOCAB; r0 += 4 * WTOT) {
            int r1 = r0 + WTOT, r2 = r0 + 2 * WTOT, r3 = r0 + 3 * WTOT;
            bool h1 = (r1 < VOCAB), h2 = (r2 < VOCAB), h3 = (r3 < VOCAB);
            const float4* p0 = (const float4*)(fc2_w + (size_t)r0 * HID);
            const float4* p1 = (const float4*)(fc2_w + (size_t)(h1 ? r1 : r0) * HID);
            const float4* p2 = (const float4*)(fc2_w + (size_t)(h2 ? r2 : r0) * HID);
            const float4* p3 = (const float4*)(fc2_w + (size_t)(h3 ? r3 : r0) * HID);
            float a0 = 0.f, a1 = 0.f, a2 = 0.f, a3 = 0.f;
#pragma unroll
            for (int i = 0; i < 8; i++) {
                int k = lane + (i << 5);
                float4 v0 = __ldcs(p0 + k);
                float4 v1 = __ldcs(p1 + k);
                float4 v2 = __ldcs(p2 + k);
                float4 v3 = __ldcs(p3 + k);
                a0 += v0.x * hreg[i].x + v0.y * hreg[i].y + v0.z * hreg[i].z + v0.w * hreg[i].w;
                a1 += v1.x * hreg[i].x + v1.y * hreg[i].y + v1.z * hreg[i].z + v1.w * hreg[i].w;
                a2 += v2.x * hreg[i].x + v2.y * hreg[i].y + v2.z * hreg[i].z + v2.w * hreg[i].w;
                a3 += v3.x * hreg[i].x + v3.y * hreg[i].y + v3.z * hreg[i].z + v3.w * hreg[i].w;
            }
            a0 = warp_sum(a0);
            a1 = warp_sum(a1);
            a2 = warp_sum(a2);
            a3 = warp_sum(a3);
            if (lane == 0) {
                float logit = a0 + fc2_b[r0];
                out[r0] = logit;
                float mm = fmaxf(lm, logit);
                ll = ll * expf(lm - mm) + expf(logit - mm);
                lm = mm;
                if (h1) {
                    logit = a1 + fc2_b[r1];
                    out[r1] = logit;
                    mm = fmaxf(lm, logit);
                    ll = ll * expf(lm - mm) + expf(logit - mm);
                    lm = mm;
                }
                if (h2) {
                    logit = a2 + fc2_b[r2];
                    out[r2] = logit;
                    mm = fmaxf(lm, logit);
                    ll = ll * expf(lm - mm) + expf(logit - mm);
                    lm = mm;
                }
                if (h3) {
                    logit = a3 + fc2_b[r3];
                    out[r3] = logit;
                    mm = fmaxf(lm, logit);
                    ll = ll * expf(lm - mm) + expf(logit - mm);
                    lm = mm;
                }
            }
        }
        if (lane == 0) { sredw[w] = lm; sredw2[w] = ll; }
        __syncthreads();
        if (w == 0) {
            float mm = (lane < 16) ? sredw[lane] : -INFINITY;
            float lll = (lane < 16) ? sredw2[lane] : 0.f;
#pragma unroll
            for (int o = 16; o; o >>= 1) {
                float m2 = __shfl_down_sync(0xffffffffu, mm, o);
                float l2 = __shfl_down_sync(0xffffffffu, lll, o);
                float M = fmaxf(mm, m2);
                lll = lll * expf(mm - M) + l2 * expf(m2 - M);
                mm = M;
            }
            if (lane == 0) { g_lse_m[b] = mm; g_lse_l[b] = lll; }
        }
    }
    grid_barrier();

    // ================= Phase 6: LSE combine (redundant per block) + float4 subtract =================
    {
        if (w == 0) {
            float mm = -INFINITY, lll = 0.f;
            for (int i = lane; i < NBLK; i += 32) {
                float m2 = g_lse_m[i], l2 = g_lse_l[i];
                float M = fmaxf(mm, m2);
                lll = lll * expf(mm - M) + l2 * expf(m2 - M);
                mm = M;
            }
#pragma unroll
            for (int o = 16; o; o >>= 1) {
                float m2 = __shfl_down_sync(0xffffffffu, mm, o);
                float l2 = __shfl_down_sync(0xffffffffu, lll, o);
                float M = fmaxf(mm, m2);
                lll = lll * expf(mm - M) + l2 * expf(m2 - M);
                mm = M;
            }
            if (lane == 0) sredw[0] = mm + logf(lll);
        }
        __syncthreads();
        float lse = sredw[0];
        const int N4 = VOCAB / 4;                // 12564
        int i4 = b * NTHR + tid;
        float4* o4 = (float4*)out;
        if (i4 < N4) {
            float4 v = o4[i4];
            v.x -= lse; v.y -= lse; v.z -= lse; v.w -= lse;
            o4[i4] = v;
        } else if (i4 == N4) {
            out[VOCAB - 1] -= lse;               // tail element
        }
    }
}

// ---------------- launch ----------------
extern "C" void kernel_launch(void* const* d_in, const int* in_sizes, int n_in,
                              void* d_out, int out_size) {
    const float* attn  = (const float*)d_in[0];
    const float* x     = (const float*)d_in[1];
    const float* h     = (const float*)d_in[2];
    const float* c     = (const float*)d_in[3];
    const float* W_ih  = (const float*)d_in[4];
    const float* W_hh  = (const float*)d_in[5];
    const float* b_ih  = (const float*)d_in[6];
    const float* b_hh  = (const float*)d_in[7];
    const float* fc1_w = (const float*)d_in[8];
    const float* fc1_b = (const float*)d_in[9];
    const float* fc2_w = (const float*)d_in[10];
    const float* fc2_b = (const float*)d_in[11];
    float* out = (float*)d_out;

    fused_all<<<NBLK, NTHR>>>(attn, x, h, c, W_ih, W_hh, b_ih, b_hh,
                              fc1_w, fc1_b, fc2_w, fc2_b, out);
}